// round 2
// baseline (speedup 1.0000x reference)
#include <cuda_runtime.h>
#include <cuda_bf16.h>
#include <cstdint>

// HalfKP NNUE forward, fully fused.
// Inputs (metadata order):
//  0 white_indices  int32  [B*BAG]
//  1 white_offsets  int64  [B]      (uniform bags -> unused)
//  2 black_indices  int32  [B*BAG]
//  3 black_offsets  int64  [B]      (unused)
//  4 ft_white  f32 [NUM_EMB, 256]
//  5 ft_black  f32 [NUM_EMB, 256]
//  6 fc1_w f32 [32, 512]   7 fc1_b f32 [32]
//  8 fc2_w f32 [32, 32]    9 fc2_b f32 [32]
// 10 fc3_w f32 [1, 32]    11 fc3_b f32 [1]
// output f32 [B]

#define H1 256

__global__ __launch_bounds__(256, 8)
void nnue_fused_kernel(const int* __restrict__ wi,
                       const int* __restrict__ bi,
                       const float* __restrict__ ftw,
                       const float* __restrict__ ftb,
                       const float* __restrict__ fc1w,
                       const float* __restrict__ fc1b,
                       const float* __restrict__ fc2w,
                       const float* __restrict__ fc2b,
                       const float* __restrict__ fc3w,
                       const float* __restrict__ fc3b,
                       float* __restrict__ out,
                       int bag)
{
    const int pos = blockIdx.x;
    const int t   = threadIdx.x;            // 0..255

    __shared__ int   sW[64];
    __shared__ int   sB[64];
    __shared__ float4 red[256];              // pair-reduction buffer
    __shared__ float  x[2 * H1];             // concat(reluW, reluB)
    __shared__ float  h1[32];

    // load indices for this position into smem
    for (int i = t; i < bag; i += 256) {
        sW[i] = wi[(size_t)pos * bag + i];
        sB[i] = bi[(size_t)pos * bag + i];
    }
    __syncthreads();

    // ---- Embedding-bag gather (float4, 2 rows in flight per table) ----
    // 128 threads per table; within a table: rgrp = which row parity (0/1),
    // c4 = which float4 column (0..63).
    const int half = t >> 7;                 // 0 = white, 1 = black
    const int sub  = t & 127;
    const int rgrp = sub >> 6;               // 0..1
    const int c4   = sub & 63;               // 0..63

    const int*   sidx  = half ? sB : sW;
    const float* table = half ? ftb : ftw;

    float4 acc = make_float4(0.f, 0.f, 0.f, 0.f);
    #pragma unroll 4
    for (int k = rgrp; k < bag; k += 2) {
        const float4 v = *reinterpret_cast<const float4*>(
            table + (size_t)sidx[k] * H1 + c4 * 4);
        acc.x += v.x; acc.y += v.y; acc.z += v.z; acc.w += v.w;
    }
    red[t] = acc;
    __syncthreads();

    // combine row-parity pairs, ReLU, scatter into x[512]
    if ((t & 64) == 0) {                     // rgrp == 0 threads
        const float4 o = red[t + 64];
        const int base = half * H1 + c4 * 4;
        x[base + 0] = fmaxf(acc.x + o.x, 0.f);
        x[base + 1] = fmaxf(acc.y + o.y, 0.f);
        x[base + 2] = fmaxf(acc.z + o.z, 0.f);
        x[base + 3] = fmaxf(acc.w + o.w, 0.f);
    }
    __syncthreads();

    // ---- fc1: 32 outputs, 8 threads per output (float4 dot over 512) ----
    const int o     = t >> 3;                // 0..31
    const int lane8 = t & 7;                 // 0..7
    const float4* x4 = reinterpret_cast<const float4*>(x);
    const float4* w4 = reinterpret_cast<const float4*>(fc1w) + o * 128;
    float s = 0.f;
    #pragma unroll
    for (int j = 0; j < 16; j++) {
        const int k = lane8 + 8 * j;         // 0..127 float4 index
        const float4 xv = x4[k];
        const float4 wv = w4[k];
        s += xv.x * wv.x + xv.y * wv.y + xv.z * wv.z + xv.w * wv.w;
    }
    s += __shfl_down_sync(0xffffffffu, s, 4);
    s += __shfl_down_sync(0xffffffffu, s, 2);
    s += __shfl_down_sync(0xffffffffu, s, 1);
    if (lane8 == 0) h1[o] = fmaxf(s + fc1b[o], 0.f);
    __syncthreads();

    // ---- fc2 + fc3: warp 0 ----
    if (t < 32) {
        float s2 = 0.f;
        #pragma unroll
        for (int k = 0; k < 32; k++) s2 += h1[k] * fc2w[t * 32 + k];
        const float h2 = fmaxf(s2 + fc2b[t], 0.f);
        float v = h2 * fc3w[t];
        #pragma unroll
        for (int off = 16; off > 0; off >>= 1)
            v += __shfl_down_sync(0xffffffffu, v, off);
        if (t == 0) out[pos] = v + fc3b[0];
    }
}

extern "C" void kernel_launch(void* const* d_in, const int* in_sizes, int n_in,
                              void* d_out, int out_size)
{
    const int*   wi   = (const int*)  d_in[0];
    const int*   bi   = (const int*)  d_in[2];
    const float* ftw  = (const float*)d_in[4];
    const float* ftb  = (const float*)d_in[5];
    const float* fc1w = (const float*)d_in[6];
    const float* fc1b = (const float*)d_in[7];
    const float* fc2w = (const float*)d_in[8];
    const float* fc2b = (const float*)d_in[9];
    const float* fc3w = (const float*)d_in[10];
    const float* fc3b = (const float*)d_in[11];
    float* out = (float*)d_out;

    const int B   = in_sizes[1];             // offsets count = batch
    const int bag = in_sizes[0] / B;         // uniform bag size (30)

    nnue_fused_kernel<<<B, 256>>>(wi, bi, ftw, ftb,
                                  fc1w, fc1b, fc2w, fc2b, fc3w, fc3b,
                                  out, bag);
}